// round 8
// baseline (speedup 1.0000x reference)
#include <cuda_runtime.h>
#include <math.h>

#define T_LEN   16
#define C_DIM   192
#define DIN     384
#define DSTATE  16
#define DTRANK  12
#define XP_OUT  44
#define DB_STR  48
#define HW      784
#define NTHR    384
#define TSTR    20

// smem layout (floats), total 13056 floats = 52224 B -> 3 CTAs/SM
#define OFF_UC 0        // uc [t][c] 6144 ; later yT [c][t] 7680
#define OFF_Z  6144     // z [t][c] 6144 (xn [c][t] 3840 aliased pre-B; y in place)
#define OFF_XN 6144
#define OFF_DB 12288    // [t][48]
#define SMEM_FLOATS 13056

__device__ __forceinline__ float siluf(float v) {
    return __fdividef(v, 1.0f + __expf(-v));
}

__global__ __launch_bounds__(NTHR, 3)
void mamba_fused_kernel(const float* __restrict__ x,
                        const float* __restrict__ norm_w,
                        const float* __restrict__ in_proj_w,   // (192, 768)
                        const float* __restrict__ conv_w,      // (384, 4)
                        const float* __restrict__ conv_b,      // (384,)
                        const float* __restrict__ x_proj_w,    // (384, 44)
                        const float* __restrict__ dt_proj_w,   // (12, 384)
                        const float* __restrict__ dt_proj_b,   // (384,)
                        const float* __restrict__ A_log,       // (384, 16)
                        const float* __restrict__ Dp,          // (384,)
                        const float* __restrict__ out_proj_w,  // (384, 192)
                        float* __restrict__ out)
{
    extern __shared__ float sm[];
    float* s_uc = sm + OFF_UC;
    float* s_z  = sm + OFF_Z;
    float* s_xn = sm + OFF_XN;
    float* s_db = sm + OFF_DB;
    float* s_yT = sm + OFF_UC;   // [c][t] stride TSTR, valid after transpose

    const int tid  = threadIdx.x;
    const int lane = tid & 31;
    const int wid  = tid >> 5;

    const int n  = blockIdx.x;
    const int b  = n / HW;
    const int hw = n - b * HW;
    const size_t tstride = (size_t)HW * C_DIM;
    const size_t base0   = ((size_t)b * T_LEN * HW + hw) * C_DIM;

    // ---------------- Phase A: load + RMSNorm -> s_xn[c][t] ----------------
    for (int t = wid; t < T_LEN; t += 12) {
        const float* row = x + base0 + (size_t)t * tstride;
        float v[6];
        float ss = 0.f;
        #pragma unroll
        for (int i = 0; i < 6; i++) { v[i] = row[lane + 32 * i]; ss = fmaf(v[i], v[i], ss); }
        #pragma unroll
        for (int o = 16; o; o >>= 1) ss += __shfl_xor_sync(0xffffffffu, ss, o);
        float nrm = rsqrtf(ss * (1.0f / 192.0f) + 1e-6f);
        #pragma unroll
        for (int i = 0; i < 6; i++) {
            int c = lane + 32 * i;
            s_xn[c * TSTR + t] = v[i] * nrm * norm_w[c];
        }
    }
    __syncthreads();

    // ---------------- Phase B: in_proj -> acc0 (u, col tid), acc1 (z) ------
    {
        float acc0[16], acc1[16];
        const float* wp = in_proj_w + tid;
        #pragma unroll
        for (int t = 0; t < 16; t++) { acc0[t] = 0.f; acc1[t] = 0.f; }

        float wa = wp[0], wb = wp[384];
        #pragma unroll 4
        for (int k = 0; k < C_DIM; k++) {
            int kn = k + 1; if (kn >= C_DIM) kn = 0;
            float nwa = wp[kn * 768];
            float nwb = wp[kn * 768 + 384];
            const float4* xp = (const float4*)(s_xn + k * TSTR);
            #pragma unroll
            for (int q = 0; q < 4; q++) {
                float4 xv = xp[q];
                acc0[4*q+0] = fmaf(xv.x, wa, acc0[4*q+0]);
                acc0[4*q+1] = fmaf(xv.y, wa, acc0[4*q+1]);
                acc0[4*q+2] = fmaf(xv.z, wa, acc0[4*q+2]);
                acc0[4*q+3] = fmaf(xv.w, wa, acc0[4*q+3]);
                acc1[4*q+0] = fmaf(xv.x, wb, acc1[4*q+0]);
                acc1[4*q+1] = fmaf(xv.y, wb, acc1[4*q+1]);
                acc1[4*q+2] = fmaf(xv.z, wb, acc1[4*q+2]);
                acc1[4*q+3] = fmaf(xv.w, wb, acc1[4*q+3]);
            }
            wa = nwa; wb = nwb;
        }
        __syncthreads();   // all warps done reading xn before z stores alias it

        // ---------------- Phase C: conv in registers; store uc + silu(z) ---
        const int c = tid;
        const float4 cw = *(const float4*)(conv_w + c * 4);
        const float cb = conv_b[c];
        float um3 = 0.f, um2 = 0.f, um1 = 0.f;
        #pragma unroll
        for (int t = 0; t < T_LEN; t++) {
            float u0 = acc0[t];
            float a = cb;
            a = fmaf(um3, cw.x, a);
            a = fmaf(um2, cw.y, a);
            a = fmaf(um1, cw.z, a);
            a = fmaf(u0,  cw.w, a);
            s_uc[t * DIN + c] = siluf(a);
            s_z[t * DIN + c]  = siluf(acc1[t]);
            um3 = um2; um2 = um1; um1 = u0;
        }
    }
    __syncthreads();

    // ---------------- Phase D: x_proj -> s_db (4 warps x 4 timesteps) ------
    // Weight stream happens 4x per CTA instead of 16x.
    if (wid < 4 && lane < 22) {
        const float2* wrow = (const float2*)x_proj_w + lane;  // row stride 22 float2
        const float* r0 = s_uc + (wid     ) * DIN;
        const float* r1 = s_uc + (wid +  4) * DIN;
        const float* r2 = s_uc + (wid +  8) * DIN;
        const float* r3 = s_uc + (wid + 12) * DIN;
        float a00=0.f,a01=0.f, a10=0.f,a11=0.f, a20=0.f,a21=0.f, a30=0.f,a31=0.f;
        #pragma unroll 2
        for (int k = 0; k < DIN; k += 4) {
            float2 w0 = wrow[(k + 0) * 22];
            float2 w1 = wrow[(k + 1) * 22];
            float2 w2 = wrow[(k + 2) * 22];
            float2 w3 = wrow[(k + 3) * 22];
            float4 u0 = *(const float4*)(r0 + k);
            float4 u1 = *(const float4*)(r1 + k);
            float4 u2 = *(const float4*)(r2 + k);
            float4 u3 = *(const float4*)(r3 + k);
            a00 = fmaf(u0.x, w0.x, a00); a01 = fmaf(u0.x, w0.y, a01);
            a00 = fmaf(u0.y, w1.x, a00); a01 = fmaf(u0.y, w1.y, a01);
            a00 = fmaf(u0.z, w2.x, a00); a01 = fmaf(u0.z, w2.y, a01);
            a00 = fmaf(u0.w, w3.x, a00); a01 = fmaf(u0.w, w3.y, a01);
            a10 = fmaf(u1.x, w0.x, a10); a11 = fmaf(u1.x, w0.y, a11);
            a10 = fmaf(u1.y, w1.x, a10); a11 = fmaf(u1.y, w1.y, a11);
            a10 = fmaf(u1.z, w2.x, a10); a11 = fmaf(u1.z, w2.y, a11);
            a10 = fmaf(u1.w, w3.x, a10); a11 = fmaf(u1.w, w3.y, a11);
            a20 = fmaf(u2.x, w0.x, a20); a21 = fmaf(u2.x, w0.y, a21);
            a20 = fmaf(u2.y, w1.x, a20); a21 = fmaf(u2.y, w1.y, a21);
            a20 = fmaf(u2.z, w2.x, a20); a21 = fmaf(u2.z, w2.y, a21);
            a20 = fmaf(u2.w, w3.x, a20); a21 = fmaf(u2.w, w3.y, a21);
            a30 = fmaf(u3.x, w0.x, a30); a31 = fmaf(u3.x, w0.y, a31);
            a30 = fmaf(u3.y, w1.x, a30); a31 = fmaf(u3.y, w1.y, a31);
            a30 = fmaf(u3.z, w2.x, a30); a31 = fmaf(u3.z, w2.y, a31);
            a30 = fmaf(u3.w, w3.x, a30); a31 = fmaf(u3.w, w3.y, a31);
        }
        *(float2*)(s_db + (wid     ) * DB_STR + 2 * lane) = make_float2(a00, a01);
        *(float2*)(s_db + (wid +  4) * DB_STR + 2 * lane) = make_float2(a10, a11);
        *(float2*)(s_db + (wid +  8) * DB_STR + 2 * lane) = make_float2(a20, a21);
        *(float2*)(s_db + (wid + 12) * DB_STR + 2 * lane) = make_float2(a30, a31);
    }
    __syncthreads();

    // ---------------- Phase E: dt_proj + softplus -> dtv[] registers -------
    float dtv[T_LEN];
    {
        const int c = tid;
        float wreg[DTRANK];
        #pragma unroll
        for (int r = 0; r < DTRANK; r++) wreg[r] = dt_proj_w[r * DIN + c];
        const float bias = dt_proj_b[c];
        #pragma unroll
        for (int t = 0; t < T_LEN; t++) {
            const float4* dr = (const float4*)(s_db + t * DB_STR);
            float4 d0 = dr[0], d1 = dr[1], d2 = dr[2];
            float a = bias;
            a = fmaf(d0.x, wreg[0],  a);
            a = fmaf(d0.y, wreg[1],  a);
            a = fmaf(d0.z, wreg[2],  a);
            a = fmaf(d0.w, wreg[3],  a);
            a = fmaf(d1.x, wreg[4],  a);
            a = fmaf(d1.y, wreg[5],  a);
            a = fmaf(d1.z, wreg[6],  a);
            a = fmaf(d1.w, wreg[7],  a);
            a = fmaf(d2.x, wreg[8],  a);
            a = fmaf(d2.y, wreg[9],  a);
            a = fmaf(d2.z, wreg[10], a);
            a = fmaf(d2.w, wreg[11], a);
            dtv[t] = (a > 20.f) ? a : log1pf(__expf(a));
        }
    }

    // ---------------- Phase F: selective scan; y overwrites z in place -----
    {
        const int c = tid;
        float A[DSTATE];
        {
            const float4* Ap = (const float4*)(A_log + c * DSTATE);
            #pragma unroll
            for (int q = 0; q < 4; q++) {
                float4 av = Ap[q];
                A[4*q+0] = -__expf(av.x); A[4*q+1] = -__expf(av.y);
                A[4*q+2] = -__expf(av.z); A[4*q+3] = -__expf(av.w);
            }
        }
        float h[DSTATE];
        #pragma unroll
        for (int s = 0; s < DSTATE; s++) h[s] = 0.f;
        const float Dc = Dp[c];

        #pragma unroll 1
        for (int t = 0; t < T_LEN; t++) {
            float dt_t = dtv[t];
            float ucv  = s_uc[t * DIN + c];
            float du   = dt_t * ucv;
            const float4* B4 = (const float4*)(s_db + t * DB_STR + DTRANK);
            const float4* C4 = (const float4*)(s_db + t * DB_STR + DTRANK + DSTATE);
            float y = 0.f;
            #pragma unroll
            for (int q = 0; q < 4; q++) {
                float4 Bv = B4[q];
                float4 Cv = C4[q];
                float dA, hb;
                dA = __expf(dt_t * A[4*q+0]); hb = fmaf(h[4*q+0], dA, du * Bv.x); h[4*q+0] = hb; y = fmaf(hb, Cv.x, y);
                dA = __expf(dt_t * A[4*q+1]); hb = fmaf(h[4*q+1], dA, du * Bv.y); h[4*q+1] = hb; y = fmaf(hb, Cv.y, y);
                dA = __expf(dt_t * A[4*q+2]); hb = fmaf(h[4*q+2], dA, du * Bv.z); h[4*q+2] = hb; y = fmaf(hb, Cv.z, y);
                dA = __expf(dt_t * A[4*q+3]); hb = fmaf(h[4*q+3], dA, du * Bv.w); h[4*q+3] = hb; y = fmaf(hb, Cv.w, y);
            }
            y = fmaf(ucv, Dc, y);
            s_z[t * DIN + c] = y * s_z[t * DIN + c];   // y in place over z
        }
    }
    __syncthreads();

    // ---------------- transpose y[t][c] (z region) -> s_yT[c][t] -----------
    {
        const int c = tid;
        float yv[16];
        #pragma unroll
        for (int t = 0; t < T_LEN; t++) yv[t] = s_z[t * DIN + c];
        __syncthreads();   // all reads staged before yT writes clobber uc/z-head
        float4* dst = (float4*)(s_yT + c * TSTR);
        dst[0] = make_float4(yv[0],  yv[1],  yv[2],  yv[3]);
        dst[1] = make_float4(yv[4],  yv[5],  yv[6],  yv[7]);
        dst[2] = make_float4(yv[8],  yv[9],  yv[10], yv[11]);
        dst[3] = make_float4(yv[12], yv[13], yv[14], yv[15]);
    }
    __syncthreads();

    // ---------------- Phase G: out_proj + residual, pipelined weights ------
    {
        const int c  = (tid < C_DIM) ? tid : (tid - C_DIM);
        const int t0 = (tid < C_DIM) ? 0 : 8;
        const float* wg = out_proj_w + c;
        float acc[8];
        #pragma unroll
        for (int i = 0; i < 8; i++) acc[i] = 0.f;

        float w0 = wg[0], w1 = wg[C_DIM];
        #pragma unroll 2
        for (int k = 0; k < DIN; k += 2) {
            int kn = k + 2; if (kn >= DIN) kn = 0;
            float nw0 = wg[kn * C_DIM];
            float nw1 = wg[kn * C_DIM + C_DIM];

            const float4* yp0 = (const float4*)(s_yT + k * TSTR + t0);
            const float4* yp1 = (const float4*)(s_yT + (k + 1) * TSTR + t0);
            float4 a0 = yp0[0], a1 = yp0[1];
            float4 b0 = yp1[0], b1 = yp1[1];
            acc[0] = fmaf(a0.x, w0, acc[0]);
            acc[1] = fmaf(a0.y, w0, acc[1]);
            acc[2] = fmaf(a0.z, w0, acc[2]);
            acc[3] = fmaf(a0.w, w0, acc[3]);
            acc[4] = fmaf(a1.x, w0, acc[4]);
            acc[5] = fmaf(a1.y, w0, acc[5]);
            acc[6] = fmaf(a1.z, w0, acc[6]);
            acc[7] = fmaf(a1.w, w0, acc[7]);
            acc[0] = fmaf(b0.x, w1, acc[0]);
            acc[1] = fmaf(b0.y, w1, acc[1]);
            acc[2] = fmaf(b0.z, w1, acc[2]);
            acc[3] = fmaf(b0.w, w1, acc[3]);
            acc[4] = fmaf(b1.x, w1, acc[4]);
            acc[5] = fmaf(b1.y, w1, acc[5]);
            acc[6] = fmaf(b1.z, w1, acc[6]);
            acc[7] = fmaf(b1.w, w1, acc[7]);
            w0 = nw0; w1 = nw1;
        }
        #pragma unroll
        for (int i = 0; i < 8; i++) {
            size_t g = base0 + (size_t)(t0 + i) * tstride + c;
            out[g] = x[g] + acc[i];
        }
    }
}

extern "C" void kernel_launch(void* const* d_in, const int* in_sizes, int n_in,
                              void* d_out, int out_size)
{
    (void)in_sizes; (void)n_in; (void)out_size;
    const float* x         = (const float*)d_in[0];
    const float* norm_w    = (const float*)d_in[1];
    const float* in_proj_w = (const float*)d_in[2];
    const float* conv_w    = (const float*)d_in[3];
    const float* conv_b    = (const float*)d_in[4];
    const float* x_proj_w  = (const float*)d_in[5];
    const float* dt_proj_w = (const float*)d_in[6];
    const float* dt_proj_b = (const float*)d_in[7];
    const float* A_log     = (const float*)d_in[8];
    const float* Dp        = (const float*)d_in[9];
    const float* out_pw    = (const float*)d_in[10];
    float* out = (float*)d_out;

    const int smem_bytes = SMEM_FLOATS * (int)sizeof(float);   // 52224 B -> 3 CTAs/SM
    cudaFuncSetAttribute(mamba_fused_kernel,
                         cudaFuncAttributeMaxDynamicSharedMemorySize, smem_bytes);

    dim3 grid(2 * HW);
    dim3 block(NTHR);
    mamba_fused_kernel<<<grid, block, smem_bytes>>>(
        x, norm_w, in_proj_w, conv_w, conv_b, x_proj_w,
        dt_proj_w, dt_proj_b, A_log, Dp, out_pw, out);
}

// round 9
// speedup vs baseline: 1.8056x; 1.8056x over previous
#include <cuda_runtime.h>
#include <cuda_bf16.h>
#include <math.h>
#include <stdint.h>

#define T_LEN  16
#define C_DIM  192
#define DIN    384
#define DSTATE 16
#define DTRANK 12
#define DB_STR 48
#define HW     784
#define NTHR   384
#define UST    388   // u / z-y row stride (floats)
#define XNS    200   // xn row stride (bf16 elems)

// fragment-ordered weights, written by prep kernel each launch
__device__ uint2 g_w1f[12 * 96 * 2 * 32];   // in_proj:  ksteps x ngroups x (hi,lo) x lane
__device__ uint2 g_w2f[24 * 24 * 2 * 32];   // out_proj

__device__ __forceinline__ float siluf(float v) {
    return __fdividef(v, 1.0f + __expf(-v));
}
__device__ __forceinline__ uint32_t bfpack(float v) {
    __nv_bfloat16 h = __float2bfloat16(v);
    __nv_bfloat16 l = __float2bfloat16(v - __bfloat162float(h));
    return (uint32_t)__bfloat16_as_ushort(h) | ((uint32_t)__bfloat16_as_ushort(l) << 16);
}
// pack two bf16 (k, k+1) into one .b32 (k in low half)
__device__ __forceinline__ uint32_t pack2bf(float a, float b, int term) {
    __nv_bfloat16 ha = __float2bfloat16(a), hb = __float2bfloat16(b);
    if (term == 0)
        return (uint32_t)__bfloat16_as_ushort(ha) | ((uint32_t)__bfloat16_as_ushort(hb) << 16);
    __nv_bfloat16 la = __float2bfloat16(a - __bfloat162float(ha));
    __nv_bfloat16 lb = __float2bfloat16(b - __bfloat162float(hb));
    return (uint32_t)__bfloat16_as_ushort(la) | ((uint32_t)__bfloat16_as_ushort(lb) << 16);
}

#define MMA_BF16(d, a0, a1, a2, a3, b0, b1)                                   \
    asm volatile("mma.sync.aligned.m16n8k16.row.col.f32.bf16.bf16.f32 "       \
                 "{%0,%1,%2,%3}, {%4,%5,%6,%7}, {%8,%9}, {%0,%1,%2,%3};"      \
                 : "+f"((d)[0]), "+f"((d)[1]), "+f"((d)[2]), "+f"((d)[3])     \
                 : "r"(a0), "r"(a1), "r"(a2), "r"(a3), "r"(b0), "r"(b1))

// ---------------- prep: swizzle weights into B-fragment order ----------------
__global__ void prep_kernel(const float* __restrict__ w1,    // (192,768)
                            const float* __restrict__ w2) {  // (384,192)
    int id = blockIdx.x * blockDim.x + threadIdx.x;
    if (id < 12 * 96 * 2 * 32) {
        int lane = id & 31, s = id >> 5, term = s & 1, r = s >> 1;
        int ng = r % 96, ks = r / 96;
        int c  = ng * 8 + (lane >> 2);
        int k0 = ks * 16 + 2 * (lane & 3);
        uint2 v;
        v.x = pack2bf(w1[k0 * 768 + c],       w1[(k0 + 1) * 768 + c], term);
        v.y = pack2bf(w1[(k0 + 8) * 768 + c], w1[(k0 + 9) * 768 + c], term);
        g_w1f[id] = v;
    } else {
        int j = id - 12 * 96 * 2 * 32;
        int lane = j & 31, s = j >> 5, term = s & 1, r = s >> 1;
        int ng = r % 24, ks = r / 24;
        int c  = ng * 8 + (lane >> 2);
        int k0 = ks * 16 + 2 * (lane & 3);
        uint2 v;
        v.x = pack2bf(w2[k0 * 192 + c],       w2[(k0 + 1) * 192 + c], term);
        v.y = pack2bf(w2[(k0 + 8) * 192 + c], w2[(k0 + 9) * 192 + c], term);
        g_w2f[j] = v;
    }
}

// ---------------- main fused kernel ----------------
// smem (bytes): xnh[16][200]bf16 @0 (6400) | xnl @6400 | u[16][388]f32 @12800 (24832)
//               | z/y[16][388] @37632 | db[16][48] @62464 (3072)  -> 65536 total
__global__ __launch_bounds__(NTHR, 3)
void mamba_fused_kernel(const float* __restrict__ x,
                        const float* __restrict__ norm_w,
                        const float* __restrict__ conv_w,
                        const float* __restrict__ conv_b,
                        const float* __restrict__ x_proj_w,
                        const float* __restrict__ dt_proj_w,
                        const float* __restrict__ dt_proj_b,
                        const float* __restrict__ A_log,
                        const float* __restrict__ Dp,
                        float* __restrict__ out)
{
    extern __shared__ char smraw[];
    __nv_bfloat16* s_xnh = (__nv_bfloat16*)(smraw);
    __nv_bfloat16* s_xnl = (__nv_bfloat16*)(smraw + 6400);
    float* s_u  = (float*)(smraw + 12800);
    float* s_zy = (float*)(smraw + 37632);
    float* s_db = (float*)(smraw + 62464);

    const int tid  = threadIdx.x;
    const int lane = tid & 31;
    const int wid  = tid >> 5;
    const int g4   = lane >> 2;        // fragment row group
    const int m2   = (lane & 3) * 2;   // fragment col pair base

    const int n  = blockIdx.x;
    const int b  = n / HW;
    const int hw = n - b * HW;
    const size_t tstride = (size_t)HW * C_DIM;
    const size_t base0   = ((size_t)b * T_LEN * HW + hw) * C_DIM;

    // ---- A: load + RMSNorm -> xn hi/lo bf16 [t][k] ----
    for (int t = wid; t < T_LEN; t += 12) {
        const float* row = x + base0 + (size_t)t * tstride;
        float v[6], ss = 0.f;
        #pragma unroll
        for (int i = 0; i < 6; i++) { v[i] = row[lane + 32 * i]; ss = fmaf(v[i], v[i], ss); }
        #pragma unroll
        for (int o = 16; o; o >>= 1) ss += __shfl_xor_sync(0xffffffffu, ss, o);
        float nrm = rsqrtf(ss * (1.0f / 192.0f) + 1e-6f);
        #pragma unroll
        for (int i = 0; i < 6; i++) {
            int c = lane + 32 * i;
            float xv = v[i] * nrm * norm_w[c];
            __nv_bfloat16 h = __float2bfloat16(xv);
            s_xnh[t * XNS + c] = h;
            s_xnl[t * XNS + c] = __float2bfloat16(xv - __bfloat162float(h));
        }
    }
    __syncthreads();

    // ---- B: in_proj via bf16 MMA (warp w -> cols w*64..w*64+63) ----
    {
        float acc[32];
        #pragma unroll
        for (int i = 0; i < 32; i++) acc[i] = 0.f;
        #pragma unroll 1
        for (int ks = 0; ks < 12; ks++) {
            int kk = ks * 16 + m2;
            uint32_t ah0 = *(const uint32_t*)(s_xnh + g4 * XNS + kk);
            uint32_t ah1 = *(const uint32_t*)(s_xnh + (g4 + 8) * XNS + kk);
            uint32_t ah2 = *(const uint32_t*)(s_xnh + g4 * XNS + kk + 8);
            uint32_t ah3 = *(const uint32_t*)(s_xnh + (g4 + 8) * XNS + kk + 8);
            uint32_t al0 = *(const uint32_t*)(s_xnl + g4 * XNS + kk);
            uint32_t al1 = *(const uint32_t*)(s_xnl + (g4 + 8) * XNS + kk);
            uint32_t al2 = *(const uint32_t*)(s_xnl + g4 * XNS + kk + 8);
            uint32_t al3 = *(const uint32_t*)(s_xnl + (g4 + 8) * XNS + kk + 8);
            #pragma unroll
            for (int ng = 0; ng < 8; ng++) {
                int gng = wid * 8 + ng;
                uint2 bh = g_w1f[((ks * 96 + gng) * 2 + 0) * 32 + lane];
                uint2 bl = g_w1f[((ks * 96 + gng) * 2 + 1) * 32 + lane];
                MMA_BF16(acc + ng * 4, ah0, ah1, ah2, ah3, bh.x, bh.y);
                MMA_BF16(acc + ng * 4, al0, al1, al2, al3, bh.x, bh.y);
                MMA_BF16(acc + ng * 4, ah0, ah1, ah2, ah3, bl.x, bl.y);
            }
        }
        // epilogue: warps 0-5 write u cols; 6-11 write silu(z) cols
        #pragma unroll
        for (int ng = 0; ng < 8; ng++) {
            int gc = wid * 64 + ng * 8 + m2;
            float d0 = acc[ng*4+0], d1 = acc[ng*4+1], d2 = acc[ng*4+2], d3 = acc[ng*4+3];
            if (gc < DIN) {
                *(float2*)(s_u + g4 * UST + gc)       = make_float2(d0, d1);
                *(float2*)(s_u + (g4 + 8) * UST + gc) = make_float2(d2, d3);
            } else {
                int zc = gc - DIN;
                *(float2*)(s_zy + g4 * UST + zc)       = make_float2(siluf(d0), siluf(d1));
                *(float2*)(s_zy + (g4 + 8) * UST + zc) = make_float2(siluf(d2), siluf(d3));
            }
        }
    }
    __syncthreads();

    // ---- C: depthwise conv + silu, in place over u (own column) ----
    {
        const int c = tid;
        const float4 cw = *(const float4*)(conv_w + c * 4);
        const float cb = conv_b[c];
        float um3 = 0.f, um2 = 0.f, um1 = 0.f;
        #pragma unroll
        for (int t = 0; t < T_LEN; t++) {
            float u0 = s_u[t * UST + c];
            float a = cb;
            a = fmaf(um3, cw.x, a);
            a = fmaf(um2, cw.y, a);
            a = fmaf(um1, cw.z, a);
            a = fmaf(u0,  cw.w, a);
            s_u[t * UST + c] = siluf(a);
            um3 = um2; um2 = um1; um1 = u0;
        }
    }
    __syncthreads();

    // ---- D: x_proj -> db (4 warps x 4 timesteps) ----
    if (wid < 4 && lane < 22) {
        const float2* wrow = (const float2*)x_proj_w + lane;
        const float* r0 = s_u + (wid     ) * UST;
        const float* r1 = s_u + (wid +  4) * UST;
        const float* r2 = s_u + (wid +  8) * UST;
        const float* r3 = s_u + (wid + 12) * UST;
        float a00=0.f,a01=0.f,a10=0.f,a11=0.f,a20=0.f,a21=0.f,a30=0.f,a31=0.f;
        #pragma unroll 2
        for (int k = 0; k < DIN; k += 4) {
            float2 w0 = wrow[(k+0)*22], w1 = wrow[(k+1)*22];
            float2 w2 = wrow[(k+2)*22], w3 = wrow[(k+3)*22];
            float4 u0 = *(const float4*)(r0+k), u1 = *(const float4*)(r1+k);
            float4 u2 = *(const float4*)(r2+k), u3 = *(const float4*)(r3+k);
            a00=fmaf(u0.x,w0.x,a00); a01=fmaf(u0.x,w0.y,a01);
            a00=fmaf(u0.y,w1.x,a00); a01=fmaf(u0.y,w1.y,a01);
            a00=fmaf(u0.z,w2.x,a00); a01=fmaf(u0.z,w2.y,a01);
            a00=fmaf(u0.w,w3.x,a00); a01=fmaf(u0.w,w3.y,a01);
            a10=fmaf(u1.x,w0.x,a10); a11=fmaf(u1.x,w0.y,a11);
            a10=fmaf(u1.y,w1.x,a10); a11=fmaf(u1.y,w1.y,a11);
            a10=fmaf(u1.z,w2.x,a10); a11=fmaf(u1.z,w2.y,a11);
            a10=fmaf(u1.w,w3.x,a10); a11=fmaf(u1.w,w3.y,a11);
            a20=fmaf(u2.x,w0.x,a20); a21=fmaf(u2.x,w0.y,a21);
            a20=fmaf(u2.y,w1.x,a20); a21=fmaf(u2.y,w1.y,a21);
            a20=fmaf(u2.z,w2.x,a20); a21=fmaf(u2.z,w2.y,a21);
            a20=fmaf(u2.w,w3.x,a20); a21=fmaf(u2.w,w3.y,a21);
            a30=fmaf(u3.x,w0.x,a30); a31=fmaf(u3.x,w0.y,a31);
            a30=fmaf(u3.y,w1.x,a30); a31=fmaf(u3.y,w1.y,a31);
            a30=fmaf(u3.z,w2.x,a30); a31=fmaf(u3.z,w2.y,a31);
            a30=fmaf(u3.w,w3.x,a30); a31=fmaf(u3.w,w3.y,a31);
        }
        *(float2*)(s_db + (wid     ) * DB_STR + 2*lane) = make_float2(a00,a01);
        *(float2*)(s_db + (wid +  4) * DB_STR + 2*lane) = make_float2(a10,a11);
        *(float2*)(s_db + (wid +  8) * DB_STR + 2*lane) = make_float2(a20,a21);
        *(float2*)(s_db + (wid + 12) * DB_STR + 2*lane) = make_float2(a30,a31);
    }
    __syncthreads();

    // ---- E: dt_proj + softplus -> registers ----
    float dtv[T_LEN];
    {
        const int c = tid;
        float wreg[DTRANK];
        #pragma unroll
        for (int r = 0; r < DTRANK; r++) wreg[r] = dt_proj_w[r * DIN + c];
        const float bias = dt_proj_b[c];
        #pragma unroll
        for (int t = 0; t < T_LEN; t++) {
            const float4* dr = (const float4*)(s_db + t * DB_STR);
            float4 d0 = dr[0], d1 = dr[1], d2 = dr[2];
            float a = bias;
            a=fmaf(d0.x,wreg[0],a); a=fmaf(d0.y,wreg[1],a); a=fmaf(d0.z,wreg[2],a); a=fmaf(d0.w,wreg[3],a);
            a=fmaf(d1.x,wreg[4],a); a=fmaf(d1.y,wreg[5],a); a=fmaf(d1.z,wreg[6],a); a=fmaf(d1.w,wreg[7],a);
            a=fmaf(d2.x,wreg[8],a); a=fmaf(d2.y,wreg[9],a); a=fmaf(d2.z,wreg[10],a); a=fmaf(d2.w,wreg[11],a);
            dtv[t] = (a > 20.f) ? a : log1pf(__expf(a));
        }
    }

    // ---- F: selective scan; y (bf16 hi/lo packed) overwrites z in place ----
    {
        const int c = tid;
        float A[DSTATE];
        const float4* Ap = (const float4*)(A_log + c * DSTATE);
        #pragma unroll
        for (int q = 0; q < 4; q++) {
            float4 av = Ap[q];
            A[4*q+0] = -__expf(av.x); A[4*q+1] = -__expf(av.y);
            A[4*q+2] = -__expf(av.z); A[4*q+3] = -__expf(av.w);
        }
        float h[DSTATE];
        #pragma unroll
        for (int s = 0; s < DSTATE; s++) h[s] = 0.f;
        const float Dc = Dp[c];
        #pragma unroll 1
        for (int t = 0; t < T_LEN; t++) {
            float dt_t = dtv[t];
            float ucv  = s_u[t * UST + c];
            float du   = dt_t * ucv;
            const float4* B4 = (const float4*)(s_db + t * DB_STR + DTRANK);
            const float4* C4 = (const float4*)(s_db + t * DB_STR + DTRANK + DSTATE);
            float y = 0.f;
            #pragma unroll
            for (int q = 0; q < 4; q++) {
                float4 Bv = B4[q], Cv = C4[q];
                float dA, hb;
                dA=__expf(dt_t*A[4*q+0]); hb=fmaf(h[4*q+0],dA,du*Bv.x); h[4*q+0]=hb; y=fmaf(hb,Cv.x,y);
                dA=__expf(dt_t*A[4*q+1]); hb=fmaf(h[4*q+1],dA,du*Bv.y); h[4*q+1]=hb; y=fmaf(hb,Cv.y,y);
                dA=__expf(dt_t*A[4*q+2]); hb=fmaf(h[4*q+2],dA,du*Bv.z); h[4*q+2]=hb; y=fmaf(hb,Cv.z,y);
                dA=__expf(dt_t*A[4*q+3]); hb=fmaf(h[4*q+3],dA,du*Bv.w); h[4*q+3]=hb; y=fmaf(hb,Cv.w,y);
            }
            y = fmaf(ucv, Dc, y);
            float yz = y * s_zy[t * UST + c];
            *(uint32_t*)(s_zy + t * UST + c) = bfpack(yz);   // packed hi|lo<<16
        }
    }
    __syncthreads();

    // ---- G: out_proj via bf16 MMA + residual (warp w -> ngroups 2w,2w+1) ----
    {
        const uint32_t* yp = (const uint32_t*)s_zy;
        float acc[8];
        #pragma unroll
        for (int i = 0; i < 8; i++) acc[i] = 0.f;
        #pragma unroll 1
        for (int ks = 0; ks < 24; ks++) {
            int kk = ks * 16 + m2;
            uint32_t p00 = yp[g4 * UST + kk],       p01 = yp[g4 * UST + kk + 1];
            uint32_t p10 = yp[(g4+8) * UST + kk],   p11 = yp[(g4+8) * UST + kk + 1];
            uint32_t p20 = yp[g4 * UST + kk + 8],   p21 = yp[g4 * UST + kk + 9];
            uint32_t p30 = yp[(g4+8) * UST + kk+8], p31 = yp[(g4+8) * UST + kk + 9];
            uint32_t ah0 = __byte_perm(p00, p01, 0x5410), al0 = __byte_perm(p00, p01, 0x7632);
            uint32_t ah1 = __byte_perm(p10, p11, 0x5410), al1 = __byte_perm(p10, p11, 0x7632);
            uint32_t ah2 = __byte_perm(p20, p21, 0x5410), al2 = __byte_perm(p20, p21, 0x7632);
            uint32_t ah3 = __byte_perm(p30, p31, 0x5410), al3 = __byte_perm(p30, p31, 0x7632);
            #pragma unroll
            for (int ng = 0; ng < 2; ng++) {
                int gng = wid * 2 + ng;
                uint2 bh = g_w2f[((ks * 24 + gng) * 2 + 0) * 32 + lane];
                uint2 bl = g_w2f[((ks * 24 + gng) * 2 + 1) * 32 + lane];
                MMA_BF16(acc + ng * 4, ah0, ah1, ah2, ah3, bh.x, bh.y);
                MMA_BF16(acc + ng * 4, al0, al1, al2, al3, bh.x, bh.y);
                MMA_BF16(acc + ng * 4, ah0, ah1, ah2, ah3, bl.x, bl.y);
            }
        }
        #pragma unroll
        for (int ng = 0; ng < 2; ng++) {
            int gc = (wid * 2 + ng) * 8 + m2;
            size_t ga = base0 + (size_t)g4 * tstride + gc;
            size_t gb = base0 + (size_t)(g4 + 8) * tstride + gc;
            float2 xa = *(const float2*)(x + ga);
            float2 xb = *(const float2*)(x + gb);
            *(float2*)(out + ga) = make_float2(xa.x + acc[ng*4+0], xa.y + acc[ng*4+1]);
            *(float2*)(out + gb) = make_float2(xb.x + acc[ng*4+2], xb.y + acc[ng*4+3]);
        }
    }
}

extern "C" void kernel_launch(void* const* d_in, const int* in_sizes, int n_in,
                              void* d_out, int out_size)
{
    (void)in_sizes; (void)n_in; (void)out_size;
    const float* x         = (const float*)d_in[0];
    const float* norm_w    = (const float*)d_in[1];
    const float* in_proj_w = (const float*)d_in[2];
    const float* conv_w    = (const float*)d_in[3];
    const float* conv_b    = (const float*)d_in[4];
    const float* x_proj_w  = (const float*)d_in[5];
    const float* dt_proj_w = (const float*)d_in[6];
    const float* dt_proj_b = (const float*)d_in[7];
    const float* A_log     = (const float*)d_in[8];
    const float* Dp        = (const float*)d_in[9];
    const float* out_pw    = (const float*)d_in[10];
    float* out = (float*)d_out;

    prep_kernel<<<432, 256>>>(in_proj_w, out_pw);   // 110592 threads exactly

    const int smem_bytes = 65536;
    cudaFuncSetAttribute(mamba_fused_kernel,
                         cudaFuncAttributeMaxDynamicSharedMemorySize, smem_bytes);
    mamba_fused_kernel<<<2 * HW, NTHR, smem_bytes>>>(
        x, norm_w, conv_w, conv_b, x_proj_w,
        dt_proj_w, dt_proj_b, A_log, Dp, out);
}

// round 11
// speedup vs baseline: 1.9314x; 1.0697x over previous
#include <cuda_runtime.h>
#include <cuda_bf16.h>
#include <math.h>
#include <stdint.h>

#define T_LEN  16
#define C_DIM  192
#define DIN    384
#define DSTATE 16
#define DTRANK 12
#define DB_STR 48
#define HW     784
#define NTHR   384
#define UST    388   // u / z row stride (floats)
#define XNS    200   // xn row stride (bf16)
#define YST    392   // y plane row stride (bf16): 384 channels + pad, conflict-free

__device__ uint2 g_w1f[12 * 96 * 2 * 32];   // in_proj fragments
__device__ uint2 g_w2f[24 * 24 * 2 * 32];   // out_proj fragments

__device__ __forceinline__ float siluf(float v) {
    return __fdividef(v, 1.0f + __expf(-v));
}
__device__ __forceinline__ uint32_t bfpack(float v) {
    __nv_bfloat16 h = __float2bfloat16(v);
    __nv_bfloat16 l = __float2bfloat16(v - __bfloat162float(h));
    return (uint32_t)__bfloat16_as_ushort(h) | ((uint32_t)__bfloat16_as_ushort(l) << 16);
}
__device__ __forceinline__ uint32_t pack2bf(float a, float b, int term) {
    __nv_bfloat16 ha = __float2bfloat16(a), hb = __float2bfloat16(b);
    if (term == 0)
        return (uint32_t)__bfloat16_as_ushort(ha) | ((uint32_t)__bfloat16_as_ushort(hb) << 16);
    __nv_bfloat16 la = __float2bfloat16(a - __bfloat162float(ha));
    __nv_bfloat16 lb = __float2bfloat16(b - __bfloat162float(hb));
    return (uint32_t)__bfloat16_as_ushort(la) | ((uint32_t)__bfloat16_as_ushort(lb) << 16);
}

#define MMA_BF16(d, a0, a1, a2, a3, b0, b1)                                   \
    asm volatile("mma.sync.aligned.m16n8k16.row.col.f32.bf16.bf16.f32 "       \
                 "{%0,%1,%2,%3}, {%4,%5,%6,%7}, {%8,%9}, {%0,%1,%2,%3};"      \
                 : "+f"((d)[0]), "+f"((d)[1]), "+f"((d)[2]), "+f"((d)[3])     \
                 : "r"(a0), "r"(a1), "r"(a2), "r"(a3), "r"(b0), "r"(b1))

__global__ void prep_kernel(const float* __restrict__ w1,
                            const float* __restrict__ w2) {
    int id = blockIdx.x * blockDim.x + threadIdx.x;
    if (id < 12 * 96 * 2 * 32) {
        int lane = id & 31, s = id >> 5, term = s & 1, r = s >> 1;
        int ng = r % 96, ks = r / 96;
        int c  = ng * 8 + (lane >> 2);
        int k0 = ks * 16 + 2 * (lane & 3);
        uint2 v;
        v.x = pack2bf(w1[k0 * 768 + c],       w1[(k0 + 1) * 768 + c], term);
        v.y = pack2bf(w1[(k0 + 8) * 768 + c], w1[(k0 + 9) * 768 + c], term);
        g_w1f[id] = v;
    } else {
        int j = id - 12 * 96 * 2 * 32;
        int lane = j & 31, s = j >> 5, term = s & 1, r = s >> 1;
        int ng = r % 24, ks = r / 24;
        int c  = ng * 8 + (lane >> 2);
        int k0 = ks * 16 + 2 * (lane & 3);
        uint2 v;
        v.x = pack2bf(w2[k0 * 192 + c],       w2[(k0 + 1) * 192 + c], term);
        v.y = pack2bf(w2[(k0 + 8) * 192 + c], w2[(k0 + 9) * 192 + c], term);
        g_w2f[j] = v;
    }
}

// smem: [0,12800)  xn hi/lo (stride 200 each) -> D partials -> yhi plane (stride 392, 12544B)
//       [12800,37632)  u [16][388] f32
//       [37632,62464)  z [16][388] f32 (scan packs y in place) -> ylo plane (stride 392, 12544B)
//       [62464,65536)  db [16][48]
__global__ __launch_bounds__(NTHR, 3)
void mamba_fused_kernel(const float* __restrict__ x,
                        const float* __restrict__ norm_w,
                        const float* __restrict__ conv_w,
                        const float* __restrict__ conv_b,
                        const float* __restrict__ x_proj_w,
                        const float* __restrict__ dt_proj_w,
                        const float* __restrict__ dt_proj_b,
                        const float* __restrict__ A_log,
                        const float* __restrict__ Dp,
                        float* __restrict__ out)
{
    extern __shared__ char smraw[];
    __nv_bfloat16* s_xnh = (__nv_bfloat16*)(smraw);
    __nv_bfloat16* s_xnl = (__nv_bfloat16*)(smraw + 6400);
    __nv_bfloat16* s_yhi = (__nv_bfloat16*)(smraw);           // after repack
    __nv_bfloat16* s_ylo = (__nv_bfloat16*)(smraw + 37632);   // after repack
    float* s_part = (float*)(smraw);                           // D partials
    float* s_u  = (float*)(smraw + 12800);
    float* s_z  = (float*)(smraw + 37632);
    float* s_db = (float*)(smraw + 62464);

    const int tid  = threadIdx.x;
    const int lane = tid & 31;
    const int wid  = tid >> 5;
    const int g4   = lane >> 2;
    const int m2   = (lane & 3) * 2;

    const int n  = blockIdx.x;
    const int b  = n / HW;
    const int hw = n - b * HW;
    const size_t tstride = (size_t)HW * C_DIM;
    const size_t base0   = ((size_t)b * T_LEN * HW + hw) * C_DIM;

    // ---- A: load + RMSNorm -> xn hi/lo ----
    for (int t = wid; t < T_LEN; t += 12) {
        const float* row = x + base0 + (size_t)t * tstride;
        float v[6], ss = 0.f;
        #pragma unroll
        for (int i = 0; i < 6; i++) { v[i] = row[lane + 32 * i]; ss = fmaf(v[i], v[i], ss); }
        #pragma unroll
        for (int o = 16; o; o >>= 1) ss += __shfl_xor_sync(0xffffffffu, ss, o);
        float nrm = rsqrtf(ss * (1.0f / 192.0f) + 1e-6f);
        #pragma unroll
        for (int i = 0; i < 6; i++) {
            int c = lane + 32 * i;
            float xv = v[i] * nrm * norm_w[c];
            __nv_bfloat16 h = __float2bfloat16(xv);
            s_xnh[t * XNS + c] = h;
            s_xnl[t * XNS + c] = __float2bfloat16(xv - __bfloat162float(h));
        }
    }
    __syncthreads();

    // ---- B: in_proj via bf16 MMA ----
    {
        float acc[32];
        #pragma unroll
        for (int i = 0; i < 32; i++) acc[i] = 0.f;
        #pragma unroll 1
        for (int ks = 0; ks < 12; ks++) {
            int kk = ks * 16 + m2;
            uint32_t ah0 = *(const uint32_t*)(s_xnh + g4 * XNS + kk);
            uint32_t ah1 = *(const uint32_t*)(s_xnh + (g4 + 8) * XNS + kk);
            uint32_t ah2 = *(const uint32_t*)(s_xnh + g4 * XNS + kk + 8);
            uint32_t ah3 = *(const uint32_t*)(s_xnh + (g4 + 8) * XNS + kk + 8);
            uint32_t al0 = *(const uint32_t*)(s_xnl + g4 * XNS + kk);
            uint32_t al1 = *(const uint32_t*)(s_xnl + (g4 + 8) * XNS + kk);
            uint32_t al2 = *(const uint32_t*)(s_xnl + g4 * XNS + kk + 8);
            uint32_t al3 = *(const uint32_t*)(s_xnl + (g4 + 8) * XNS + kk + 8);
            #pragma unroll
            for (int ng = 0; ng < 8; ng++) {
                int gng = wid * 8 + ng;
                uint2 bh = g_w1f[((ks * 96 + gng) * 2 + 0) * 32 + lane];
                uint2 bl = g_w1f[((ks * 96 + gng) * 2 + 1) * 32 + lane];
                MMA_BF16(acc + ng * 4, ah0, ah1, ah2, ah3, bh.x, bh.y);
                MMA_BF16(acc + ng * 4, al0, al1, al2, al3, bh.x, bh.y);
                MMA_BF16(acc + ng * 4, ah0, ah1, ah2, ah3, bl.x, bl.y);
            }
        }
        #pragma unroll
        for (int ng = 0; ng < 8; ng++) {
            int gc = wid * 64 + ng * 8 + m2;
            float d0 = acc[ng*4+0], d1 = acc[ng*4+1], d2 = acc[ng*4+2], d3 = acc[ng*4+3];
            if (gc < DIN) {
                *(float2*)(s_u + g4 * UST + gc)       = make_float2(d0, d1);
                *(float2*)(s_u + (g4 + 8) * UST + gc) = make_float2(d2, d3);
            } else {
                int zc = gc - DIN;
                *(float2*)(s_z + g4 * UST + zc)       = make_float2(siluf(d0), siluf(d1));
                *(float2*)(s_z + (g4 + 8) * UST + zc) = make_float2(siluf(d2), siluf(d3));
            }
        }
    }
    __syncthreads();

    // ---- C: depthwise conv + silu, in place over u ----
    {
        const int c = tid;
        const float4 cw = *(const float4*)(conv_w + c * 4);
        const float cb = conv_b[c];
        float um3 = 0.f, um2 = 0.f, um1 = 0.f;
        #pragma unroll
        for (int t = 0; t < T_LEN; t++) {
            float u0 = s_u[t * UST + c];
            float a = cb;
            a = fmaf(um3, cw.x, a);
            a = fmaf(um2, cw.y, a);
            a = fmaf(um1, cw.z, a);
            a = fmaf(u0,  cw.w, a);
            s_u[t * UST + c] = siluf(a);
            um3 = um2; um2 = um1; um1 = u0;
        }
    }
    __syncthreads();

    // ---- D: x_proj split-k across 12 warps (tg = wid&3, kseg = wid>>2) ----
    {
        const int tg  = wid & 3;
        const int ksg = wid >> 2;
        if (lane < 22) {
            const float2* wrow = (const float2*)x_proj_w + lane;
            const int k0 = ksg * 128;
            const float* r0 = s_u + (tg     ) * UST;
            const float* r1 = s_u + (tg +  4) * UST;
            const float* r2 = s_u + (tg +  8) * UST;
            const float* r3 = s_u + (tg + 12) * UST;
            float a00=0.f,a01=0.f,a10=0.f,a11=0.f,a20=0.f,a21=0.f,a30=0.f,a31=0.f;
            #pragma unroll 2
            for (int k = k0; k < k0 + 128; k += 4) {
                float2 w0 = wrow[(k+0)*22], w1 = wrow[(k+1)*22];
                float2 w2 = wrow[(k+2)*22], w3 = wrow[(k+3)*22];
                float4 u0 = *(const float4*)(r0+k), u1 = *(const float4*)(r1+k);
                float4 u2 = *(const float4*)(r2+k), u3 = *(const float4*)(r3+k);
                a00=fmaf(u0.x,w0.x,a00); a01=fmaf(u0.x,w0.y,a01);
                a00=fmaf(u0.y,w1.x,a00); a01=fmaf(u0.y,w1.y,a01);
                a00=fmaf(u0.z,w2.x,a00); a01=fmaf(u0.z,w2.y,a01);
                a00=fmaf(u0.w,w3.x,a00); a01=fmaf(u0.w,w3.y,a01);
                a10=fmaf(u1.x,w0.x,a10); a11=fmaf(u1.x,w0.y,a11);
                a10=fmaf(u1.y,w1.x,a10); a11=fmaf(u1.y,w1.y,a11);
                a10=fmaf(u1.z,w2.x,a10); a11=fmaf(u1.z,w2.y,a11);
                a10=fmaf(u1.w,w3.x,a10); a11=fmaf(u1.w,w3.y,a11);
                a20=fmaf(u2.x,w0.x,a20); a21=fmaf(u2.x,w0.y,a21);
                a20=fmaf(u2.y,w1.x,a20); a21=fmaf(u2.y,w1.y,a21);
                a20=fmaf(u2.z,w2.x,a20); a21=fmaf(u2.z,w2.y,a21);
                a20=fmaf(u2.w,w3.x,a20); a21=fmaf(u2.w,w3.y,a21);
                a30=fmaf(u3.x,w0.x,a30); a31=fmaf(u3.x,w0.y,a31);
                a30=fmaf(u3.y,w1.x,a30); a31=fmaf(u3.y,w1.y,a31);
                a30=fmaf(u3.z,w2.x,a30); a31=fmaf(u3.z,w2.y,a31);
                a30=fmaf(u3.w,w3.x,a30); a31=fmaf(u3.w,w3.y,a31);
            }
            float* pp = s_part + ksg * 768;
            *(float2*)(pp + (tg     ) * DB_STR + 2*lane) = make_float2(a00,a01);
            *(float2*)(pp + (tg +  4) * DB_STR + 2*lane) = make_float2(a10,a11);
            *(float2*)(pp + (tg +  8) * DB_STR + 2*lane) = make_float2(a20,a21);
            *(float2*)(pp + (tg + 12) * DB_STR + 2*lane) = make_float2(a30,a31);
        }
    }
    __syncthreads();
    if (tid < 352) {
        int t = tid / 22, j = tid - t * 22;
        int o = t * DB_STR + 2 * j;
        float2 p0 = *(const float2*)(s_part + o);
        float2 p1 = *(const float2*)(s_part + 768 + o);
        float2 p2 = *(const float2*)(s_part + 1536 + o);
        *(float2*)(s_db + o) = make_float2(p0.x + p1.x + p2.x, p0.y + p1.y + p2.y);
    }
    __syncthreads();

    // ---- E: dt_proj + softplus -> registers ----
    float dtv[T_LEN];
    {
        const int c = tid;
        float wreg[DTRANK];
        #pragma unroll
        for (int r = 0; r < DTRANK; r++) wreg[r] = dt_proj_w[r * DIN + c];
        const float bias = dt_proj_b[c];
        #pragma unroll
        for (int t = 0; t < T_LEN; t++) {
            const float4* dr = (const float4*)(s_db + t * DB_STR);
            float4 d0 = dr[0], d1 = dr[1], d2 = dr[2];
            float a = bias;
            a=fmaf(d0.x,wreg[0],a); a=fmaf(d0.y,wreg[1],a); a=fmaf(d0.z,wreg[2],a); a=fmaf(d0.w,wreg[3],a);
            a=fmaf(d1.x,wreg[4],a); a=fmaf(d1.y,wreg[5],a); a=fmaf(d1.z,wreg[6],a); a=fmaf(d1.w,wreg[7],a);
            a=fmaf(d2.x,wreg[8],a); a=fmaf(d2.y,wreg[9],a); a=fmaf(d2.z,wreg[10],a); a=fmaf(d2.w,wreg[11],a);
            dtv[t] = (a > 20.f) ? a : log1pf(__expf(a));
        }
    }

    // ---- F: selective scan; packed y (hi|lo) over z in place (own element) ----
    {
        const int c = tid;
        float A[DSTATE];
        const float4* Ap = (const float4*)(A_log + c * DSTATE);
        #pragma unroll
        for (int q = 0; q < 4; q++) {
            float4 av = Ap[q];
            A[4*q+0] = -__expf(av.x); A[4*q+1] = -__expf(av.y);
            A[4*q+2] = -__expf(av.z); A[4*q+3] = -__expf(av.w);
        }
        float h[DSTATE];
        #pragma unroll
        for (int s = 0; s < DSTATE; s++) h[s] = 0.f;
        const float Dc = Dp[c];
        #pragma unroll 1
        for (int t = 0; t < T_LEN; t++) {
            float dt_t = dtv[t];
            float ucv  = s_u[t * UST + c];
            float du   = dt_t * ucv;
            const float4* B4 = (const float4*)(s_db + t * DB_STR + DTRANK);
            const float4* C4 = (const float4*)(s_db + t * DB_STR + DTRANK + DSTATE);
            float y = 0.f;
            #pragma unroll
            for (int q = 0; q < 4; q++) {
                float4 Bv = B4[q], Cv = C4[q];
                float dA, hb;
                dA=__expf(dt_t*A[4*q+0]); hb=fmaf(h[4*q+0],dA,du*Bv.x); h[4*q+0]=hb; y=fmaf(hb,Cv.x,y);
                dA=__expf(dt_t*A[4*q+1]); hb=fmaf(h[4*q+1],dA,du*Bv.y); h[4*q+1]=hb; y=fmaf(hb,Cv.y,y);
                dA=__expf(dt_t*A[4*q+2]); hb=fmaf(h[4*q+2],dA,du*Bv.z); h[4*q+2]=hb; y=fmaf(hb,Cv.z,y);
                dA=__expf(dt_t*A[4*q+3]); hb=fmaf(h[4*q+3],dA,du*Bv.w); h[4*q+3]=hb; y=fmaf(hb,Cv.w,y);
            }
            y = fmaf(ucv, Dc, y);
            float yz = y * s_z[t * UST + c];
            *(uint32_t*)(s_z + t * UST + c) = bfpack(yz);
        }
    }

    // ---- repack: own column packed y -> yhi plane (xn region) + ylo plane (z base)
    {
        const int c = tid;
        uint32_t yv[T_LEN];
        #pragma unroll
        for (int t = 0; t < T_LEN; t++) yv[t] = *(const uint32_t*)(s_z + t * UST + c);
        __syncthreads();   // everyone staged before planes clobber xn/z regions
        uint16_t* ph = (uint16_t*)s_yhi;
        uint16_t* pl = (uint16_t*)s_ylo;
        #pragma unroll
        for (int t = 0; t < T_LEN; t++) {
            ph[t * YST + c] = (uint16_t)(yv[t] & 0xffff);
            pl[t * YST + c] = (uint16_t)(yv[t] >> 16);
        }
    }
    __syncthreads();

    // ---- G: out_proj via bf16 MMA + residual (clean plane loads) ----
    {
        float acc[8];
        #pragma unroll
        for (int i = 0; i < 8; i++) acc[i] = 0.f;
        #pragma unroll 1
        for (int ks = 0; ks < 24; ks++) {
            int kk = ks * 16 + m2;
            uint2 bh0 = g_w2f[((ks * 24 + wid * 2 + 0) * 2 + 0) * 32 + lane];
            uint2 bl0 = g_w2f[((ks * 24 + wid * 2 + 0) * 2 + 1) * 32 + lane];
            uint2 bh1 = g_w2f[((ks * 24 + wid * 2 + 1) * 2 + 0) * 32 + lane];
            uint2 bl1 = g_w2f[((ks * 24 + wid * 2 + 1) * 2 + 1) * 32 + lane];
            uint32_t ah0 = *(const uint32_t*)(s_yhi + g4 * YST + kk);
            uint32_t ah1 = *(const uint32_t*)(s_yhi + (g4 + 8) * YST + kk);
            uint32_t ah2 = *(const uint32_t*)(s_yhi + g4 * YST + kk + 8);
            uint32_t ah3 = *(const uint32_t*)(s_yhi + (g4 + 8) * YST + kk + 8);
            uint32_t al0 = *(const uint32_t*)(s_ylo + g4 * YST + kk);
            uint32_t al1 = *(const uint32_t*)(s_ylo + (g4 + 8) * YST + kk);
            uint32_t al2 = *(const uint32_t*)(s_ylo + g4 * YST + kk + 8);
            uint32_t al3 = *(const uint32_t*)(s_ylo + (g4 + 8) * YST + kk + 8);
            MMA_BF16(acc + 0, ah0, ah1, ah2, ah3, bh0.x, bh0.y);
            MMA_BF16(acc + 0, al0, al1, al2, al3, bh0.x, bh0.y);
            MMA_BF16(acc + 0, ah0, ah1, ah2, ah3, bl0.x, bl0.y);
            MMA_BF16(acc + 4, ah0, ah1, ah2, ah3, bh1.x, bh1.y);
            MMA_BF16(acc + 4, al0, al1, al2, al3, bh1.x, bh1.y);
            MMA_BF16(acc + 4, ah0, ah1, ah2, ah3, bl1.x, bl1.y);
        }
        #pragma unroll
        for (int ng = 0; ng < 2; ng++) {
            int gc = (wid * 2 + ng) * 8 + m2;
            size_t ga = base0 + (size_t)g4 * tstride + gc;
            size_t gb = base0 + (size_t)(g4 + 8) * tstride + gc;
            float2 xa = *(const float2*)(x + ga);
            float2 xb = *(const float2*)(x + gb);
            *(float2*)(out + ga) = make_float2(xa.x + acc[ng*4+0], xa.y + acc[ng*4+1]);
            *(float2*)(out + gb) = make_float2(xb.x + acc[ng*4+2], xb.y + acc[ng*4+3]);
        }
    }
}

extern "C" void kernel_launch(void* const* d_in, const int* in_sizes, int n_in,
                              void* d_out, int out_size)
{
    (void)in_sizes; (void)n_in; (void)out_size;
    const float* x         = (const float*)d_in[0];
    const float* norm_w    = (const float*)d_in[1];
    const float* in_proj_w = (const float*)d_in[2];
    const float* conv_w    = (const float*)d_in[3];
    const float* conv_b    = (const float*)d_in[4];
    const float* x_proj_w  = (const float*)d_in[5];
    const float* dt_proj_w = (const float*)d_in[6];
    const float* dt_proj_b = (const float*)d_in[7];
    const float* A_log     = (const float*)d_in[8];
    const float* Dp        = (const float*)d_in[9];
    const float* out_pw    = (const float*)d_in[10];
    float* out = (float*)d_out;

    prep_kernel<<<432, 256>>>(in_proj_w, out_pw);

    const int smem_bytes = 65536;
    cudaFuncSetAttribute(mamba_fused_kernel,
                         cudaFuncAttributeMaxDynamicSharedMemorySize, smem_bytes);
    mamba_fused_kernel<<<2 * HW, NTHR, smem_bytes>>>(
        x, norm_w, conv_w, conv_b, x_proj_w,
        dt_proj_w, dt_proj_b, A_log, Dp, out);
}